// round 8
// baseline (speedup 1.0000x reference)
#include <cuda_runtime.h>
#include <cstdint>

#define N_USERS 100000
#define N_ITEMS 60000
#define N_NODES 160000
#define D 64
#define D4 16              // D in float4 units
#define NNZ 1280000
#define NNZ_PAD (NNZ + 3 * N_NODES)   // capacity with per-row pad to multiple of 4
#define EPS 0.1f
#define SCAN_BS 1024
#define NB_SCAN ((N_NODES + SCAN_BS - 1) / SCAN_BS)   // 157

// ---------------- scratch (static device globals; no allocation) -------------
__device__ int   g_cnt[N_NODES];                 // zero-init invariant
__device__ int   g_rowptr[N_NODES + 1];          // PADDED exclusive prefix
__device__ int   g_cursor[N_NODES];
__device__ unsigned long long g_state[NB_SCAN];  // decoupled-lookback state
__device__ __align__(16) int2 g_edges[NNZ_PAD];  // packed (col, val-bits), padded
__device__ float g_ego1[(size_t)N_NODES * D];
__device__ float g_ego2[(size_t)N_NODES * D];

// ---------------- histogram (block 0 also resets lookback state) -------------
__global__ void k_hist(const int* __restrict__ rows) {
    if (blockIdx.x == 0 && threadIdx.x < NB_SCAN) g_state[threadIdx.x] = 0ULL;
    int e = blockIdx.x * blockDim.x + threadIdx.x;
    if (e < NNZ) atomicAdd(&g_cnt[rows[e]], 1);
}

// ---------------- single-pass exclusive scan (padded) + pad-edge fill --------
__global__ void k_scan() {
    __shared__ int wsum[32];
    __shared__ int s_running;
    const int bid  = blockIdx.x;
    const int i    = bid * SCAN_BS + threadIdx.x;
    const int lane = threadIdx.x & 31;
    const int wid  = threadIdx.x >> 5;

    int v = (i < N_NODES) ? g_cnt[i] : 0;
    if (i < N_NODES) g_cnt[i] = 0;               // restore invariant
    const int pv = (v + 3) & ~3;                 // padded count (multiple of 4)

    int s = pv;
    #pragma unroll
    for (int d = 1; d < 32; d <<= 1) {
        int t = __shfl_up_sync(0xffffffffu, s, d);
        if (lane >= d) s += t;
    }
    if (lane == 31) wsum[wid] = s;
    __syncthreads();
    if (wid == 0) {
        int ws = wsum[lane];
        #pragma unroll
        for (int d = 1; d < 32; d <<= 1) {
            int t = __shfl_up_sync(0xffffffffu, ws, d);
            if (lane >= d) ws += t;
        }
        wsum[lane] = ws;
    }
    __syncthreads();
    const int incl  = s + (wid ? wsum[wid - 1] : 0);
    const int total = wsum[31];

    if (threadIdx.x == 0) {
        unsigned long long pk = ((bid == 0) ? (2ULL << 32) : (1ULL << 32))
                                | (unsigned)total;
        __threadfence();
        atomicExch(&g_state[bid], pk);
        if (bid == 0) s_running = 0;
    }

    if (wid == 0 && bid > 0) {
        int running = 0;
        int pb = bid - 1;
        while (true) {
            int idx = pb - lane;
            unsigned long long st = 0ULL;
            if (idx >= 0) {
                do {
                    st = *(volatile unsigned long long*)&g_state[idx];
                } while ((st >> 32) == 0ULL);
            }
            unsigned pm = __ballot_sync(0xffffffffu, (idx >= 0) && ((st >> 32) == 2ULL));
            int val = (idx >= 0) ? (int)(st & 0xffffffffULL) : 0;
            if (pm) {
                int fp = __ffs(pm) - 1;
                int contrib = (lane <= fp) ? val : 0;
                #pragma unroll
                for (int m = 16; m; m >>= 1) contrib += __shfl_xor_sync(0xffffffffu, contrib, m);
                running += contrib;
                break;
            } else {
                int contrib = val;
                #pragma unroll
                for (int m = 16; m; m >>= 1) contrib += __shfl_xor_sync(0xffffffffu, contrib, m);
                running += contrib;
                pb -= 32;
            }
        }
        if (lane == 0) {
            __threadfence();
            atomicExch(&g_state[bid], (2ULL << 32) | (unsigned)(total + running));
            s_running = running;
        }
    }
    __syncthreads();

    const int excl = incl - pv + s_running;      // padded exclusive prefix
    if (i < N_NODES) {
        g_rowptr[i] = excl;
        g_cursor[i] = excl;
        // fill the 0-3 pad slots with null edges (col 0, val 0.0f -> exact no-op)
        #pragma unroll
        for (int j = 0; j < 3; ++j)
            if (v + j < pv) g_edges[excl + v + j] = make_int2(0, 0);
        if (i == N_NODES - 1) g_rowptr[N_NODES] = excl + pv;
    }
}

// ---------------- scatter COO -> padded CSR ----------------------------------
__global__ void k_scatter(const int* __restrict__ rows,
                          const int* __restrict__ cols,
                          const float* __restrict__ vals) {
    int e = blockIdx.x * blockDim.x + threadIdx.x;
    if (e < NNZ) {
        int r = rows[e];
        int p = atomicAdd(&g_cursor[r], 1);
        g_edges[p] = make_int2(cols[e], __float_as_int(vals[e]));
    }
}

// ---------------- fused SpMM + noise-perturb + epilogue ----------------------
// TWO rows per warp via half-warps; lane holds a float4. Row degree is padded
// to a multiple of 4, so the edge walk is ONLY whole quads (no remainder).
// Quads fetched as 2x int4 (LDG.128); software-pipelined prefetch of the next
// quad; 32-bit gather offsets.
template <int K>
__global__ void __launch_bounds__(256, 6)
k_spmm(const float4* __restrict__ xu,
       const float4* __restrict__ xi_adj,          // xi - N_USERS*D4 (only formed)
       const float4* __restrict__ noise,           // offset to layer K
       const float4* __restrict__ prevA,           // K==2: ego1
       const float4* __restrict__ prevB,           // K==2: ego2
       float4* __restrict__ yout,                  // K==0/1
       float4* __restrict__ out4)                  // d_out as float4
{
    const int gw   = (blockIdx.x * blockDim.x + threadIdx.x) >> 5;
    const int lane = threadIdx.x & 31;
    const int half = lane >> 4;
    const unsigned fl = lane & 15;
    const int row  = gw * 2 + half;
    if (row >= N_NODES) return;

    const size_t off = (size_t)row * D4 + fl;
    const float4 nk  = __ldcs(noise + off);
    const int p   = __ldg(&g_rowptr[row]);
    const int end = __ldg(&g_rowptr[row + 1]);

    float4 acc = make_float4(0.f, 0.f, 0.f, 0.f);

    #define GATHERC(c) __ldg((((c) < N_USERS) ? xu : xi_adj) + ((unsigned)(c) * D4 + fl))
    #define FMA4(v, t) do { \
        acc.x = fmaf((v), (t).x, acc.x); \
        acc.y = fmaf((v), (t).y, acc.y); \
        acc.z = fmaf((v), (t).z, acc.z); \
        acc.w = fmaf((v), (t).w, acc.w); } while (0)

    int ntrip = (end - p) >> 2;                  // always whole quads
    if (ntrip) {
        const int4* ep = reinterpret_cast<const int4*>(g_edges + p);  // 16B-aligned
        int4 a = __ldg(ep);                      // (c0,v0,c1,v1)
        int4 b = __ldg(ep + 1);                  // (c2,v2,c3,v3)
        for (int t = 1; t < ntrip; ++t) {
            const float4 t0 = GATHERC(a.x);
            const float4 t1 = GATHERC(a.z);
            const float4 t2 = GATHERC(b.x);
            const float4 t3 = GATHERC(b.z);
            const int4 na = __ldg(ep + 2 * t);
            const int4 nb = __ldg(ep + 2 * t + 1);
            FMA4(__int_as_float(a.y), t0);
            FMA4(__int_as_float(a.w), t1);
            FMA4(__int_as_float(b.y), t2);
            FMA4(__int_as_float(b.w), t3);
            a = na; b = nb;
        }
        const float4 t0 = GATHERC(a.x);
        const float4 t1 = GATHERC(a.z);
        const float4 t2 = GATHERC(b.x);
        const float4 t3 = GATHERC(b.z);
        FMA4(__int_as_float(a.y), t0);
        FMA4(__int_as_float(a.w), t1);
        FMA4(__int_as_float(b.y), t2);
        FMA4(__int_as_float(b.w), t3);
    }
    #undef GATHERC
    #undef FMA4

    // noise perturbation: ego += sign(ego) * (n / max(||n||, 1e-12)) * EPS
    float ss = nk.x * nk.x + nk.y * nk.y + nk.z * nk.z + nk.w * nk.w;
    #pragma unroll
    for (int m = 8; m; m >>= 1) ss += __shfl_xor_sync(0xffffffffu, ss, m);
    const float inv = EPS / fmaxf(sqrtf(ss), 1e-12f);
    float4 r = acc;
    r.x += ((acc.x > 0.f) ? 1.f : ((acc.x < 0.f) ? -1.f : 0.f)) * nk.x * inv;
    r.y += ((acc.y > 0.f) ? 1.f : ((acc.y < 0.f) ? -1.f : 0.f)) * nk.y * inv;
    r.z += ((acc.z > 0.f) ? 1.f : ((acc.z < 0.f) ? -1.f : 0.f)) * nk.z * inv;
    r.w += ((acc.w > 0.f) ? 1.f : ((acc.w < 0.f) ? -1.f : 0.f)) * nk.w * inv;

    if (K == 0) {
        yout[off] = r;                                     // ego1
        __stcs(out4 + (size_t)N_NODES * D4 + off, r);      // CL region
    } else if (K == 1) {
        yout[off] = r;                                     // ego2
    } else {
        const float4 pa = __ldcs(prevA + off);             // ego1: last use
        const float4 pb = __ldg(prevB + off);              // ego2: L2-hot
        const float third = 1.f / 3.f;
        float4 f;
        f.x = (pa.x + pb.x + r.x) * third;
        f.y = (pa.y + pb.y + r.y) * third;
        f.z = (pa.z + pb.z + r.z) * third;
        f.w = (pa.w + pb.w + r.w) * third;
        __stcs(out4 + off, f);                             // final region
    }
}

// ---------------- launch ------------------------------------------------------
extern "C" void kernel_launch(void* const* d_in, const int* in_sizes, int n_in,
                              void* d_out, int out_size) {
    const float* user_emb = (const float*)d_in[0];
    const float* item_emb = (const float*)d_in[1];
    const float* adj_vals = (const float*)d_in[2];
    const float* noise    = (const float*)d_in[3];
    const int*   adj_rows = (const int*)d_in[4];
    const int*   adj_cols = (const int*)d_in[5];
    float4* out4 = (float4*)d_out;

    // --- build padded CSR from COO ---
    k_hist<<<NNZ / 256, 256>>>(adj_rows);
    k_scan<<<NB_SCAN, SCAN_BS>>>();
    k_scatter<<<NNZ / 256, 256>>>(adj_rows, adj_cols, adj_vals);

    static float4* ego1 = nullptr;
    static float4* ego2 = nullptr;
    if (!ego1) {
        void* p;
        cudaGetSymbolAddress(&p, g_ego1); ego1 = (float4*)p;
        cudaGetSymbolAddress(&p, g_ego2); ego2 = (float4*)p;
    }

    const float4* noise4 = (const float4*)noise;
    const int threads = 256;                               // 8 warps = 16 rows/block
    const int blocks  = N_NODES / 16;                      // 10000

    // layer 0: split tables; xi_adj = item_emb - N_USERS*D4 (pointer only formed)
    k_spmm<0><<<blocks, threads>>>((const float4*)user_emb,
                                   (const float4*)item_emb - (size_t)N_USERS * D4,
                                   noise4,
                                   nullptr, nullptr, ego1, out4);
    // layer 1: x = ego1 contiguous -> xi_adj == xu
    k_spmm<1><<<blocks, threads>>>((const float4*)ego1,
                                   (const float4*)ego1,
                                   noise4 + (size_t)1 * N_NODES * D4,
                                   nullptr, nullptr, ego2, out4);
    // layer 2: x = ego2; epilogue writes final = (ego1+ego2+ego3)/3
    k_spmm<2><<<blocks, threads>>>((const float4*)ego2,
                                   (const float4*)ego2,
                                   noise4 + (size_t)2 * N_NODES * D4,
                                   (const float4*)ego1, (const float4*)ego2,
                                   nullptr, out4);
}

// round 9
// speedup vs baseline: 1.0592x; 1.0592x over previous
#include <cuda_runtime.h>
#include <cstdint>

#define N_USERS 100000
#define N_ITEMS 60000
#define N_NODES 160000
#define D 64
#define D4 16              // D in float4 units
#define NNZ 1280000
#define EPS 0.1f
#define SCAN_BS 1024
#define NB_SCAN ((N_NODES + SCAN_BS - 1) / SCAN_BS)   // 157

// ---------------- scratch (static device globals; no allocation) -------------
__device__ int   g_cnt[N_NODES];                 // zero-init invariant
__device__ int   g_rowptr[N_NODES + 1];
__device__ int   g_cursor[N_NODES];
__device__ unsigned long long g_state[NB_SCAN];  // decoupled-lookback state
__device__ int2  g_edges[NNZ];                   // packed (col, val-bits)
__device__ float g_ego1[(size_t)N_NODES * D];
__device__ float g_ego2[(size_t)N_NODES * D];

// ---------------- histogram (block 0 also resets lookback state) -------------
__global__ void k_hist(const int* __restrict__ rows) {
    if (blockIdx.x == 0 && threadIdx.x < NB_SCAN) g_state[threadIdx.x] = 0ULL;
    int e = blockIdx.x * blockDim.x + threadIdx.x;
    if (e < NNZ) atomicAdd(&g_cnt[rows[e]], 1);
}

// ---------------- single-pass exclusive scan with decoupled lookback ---------
__global__ void k_scan() {
    __shared__ int wsum[32];
    __shared__ int s_running;
    const int bid  = blockIdx.x;
    const int i    = bid * SCAN_BS + threadIdx.x;
    const int lane = threadIdx.x & 31;
    const int wid  = threadIdx.x >> 5;

    int v = (i < N_NODES) ? g_cnt[i] : 0;
    if (i < N_NODES) g_cnt[i] = 0;

    int s = v;
    #pragma unroll
    for (int d = 1; d < 32; d <<= 1) {
        int t = __shfl_up_sync(0xffffffffu, s, d);
        if (lane >= d) s += t;
    }
    if (lane == 31) wsum[wid] = s;
    __syncthreads();
    if (wid == 0) {
        int ws = wsum[lane];
        #pragma unroll
        for (int d = 1; d < 32; d <<= 1) {
            int t = __shfl_up_sync(0xffffffffu, ws, d);
            if (lane >= d) ws += t;
        }
        wsum[lane] = ws;
    }
    __syncthreads();
    const int incl  = s + (wid ? wsum[wid - 1] : 0);
    const int total = wsum[31];

    if (threadIdx.x == 0) {
        unsigned long long pk = ((bid == 0) ? (2ULL << 32) : (1ULL << 32))
                                | (unsigned)total;
        __threadfence();
        atomicExch(&g_state[bid], pk);
        if (bid == 0) { s_running = 0; g_rowptr[N_NODES] = NNZ; }
    }

    if (wid == 0 && bid > 0) {
        int running = 0;
        int pb = bid - 1;
        while (true) {
            int idx = pb - lane;
            unsigned long long st = 0ULL;
            if (idx >= 0) {
                do {
                    st = *(volatile unsigned long long*)&g_state[idx];
                } while ((st >> 32) == 0ULL);
            }
            unsigned pm = __ballot_sync(0xffffffffu, (idx >= 0) && ((st >> 32) == 2ULL));
            int val = (idx >= 0) ? (int)(st & 0xffffffffULL) : 0;
            if (pm) {
                int fp = __ffs(pm) - 1;
                int contrib = (lane <= fp) ? val : 0;
                #pragma unroll
                for (int m = 16; m; m >>= 1) contrib += __shfl_xor_sync(0xffffffffu, contrib, m);
                running += contrib;
                break;
            } else {
                int contrib = val;
                #pragma unroll
                for (int m = 16; m; m >>= 1) contrib += __shfl_xor_sync(0xffffffffu, contrib, m);
                running += contrib;
                pb -= 32;
            }
        }
        if (lane == 0) {
            __threadfence();
            atomicExch(&g_state[bid], (2ULL << 32) | (unsigned)(total + running));
            s_running = running;
        }
    }
    __syncthreads();

    const int excl = incl - v + s_running;
    if (i < N_NODES) { g_rowptr[i] = excl; g_cursor[i] = excl; }
}

// ---------------- scatter COO -> CSR (packed edges) ---------------------------
__global__ void k_scatter(const int* __restrict__ rows,
                          const int* __restrict__ cols,
                          const float* __restrict__ vals) {
    int e = blockIdx.x * blockDim.x + threadIdx.x;
    if (e < NNZ) {
        int r = rows[e];
        int p = atomicAdd(&g_cursor[r], 1);
        g_edges[p] = make_int2(cols[e], __float_as_int(vals[e]));
    }
}

// ---------------- fused SpMM + noise-perturb + epilogue ----------------------
// TWO rows per warp via half-warps; lane holds a float4. Unguarded unroll-4
// with software-prefetched edge quads; 32-bit gather offsets. Noise is loaded
// AFTER the edge walk so its registers are not live across the loop -> fits
// 7 blocks/SM (lb(256,7), target <=36 regs, 87.5% occupancy).
template <int K>
__global__ void __launch_bounds__(256, 7)
k_spmm(const float4* __restrict__ xu,
       const float4* __restrict__ xi_adj,          // xi - N_USERS*D4 (only formed)
       const float4* __restrict__ noise,           // offset to layer K
       const float4* __restrict__ prevA,           // K==2: ego1
       const float4* __restrict__ prevB,           // K==2: ego2
       float4* __restrict__ yout,                  // K==0/1
       float4* __restrict__ out4)                  // d_out as float4
{
    const int gw   = (blockIdx.x * blockDim.x + threadIdx.x) >> 5;
    const int lane = threadIdx.x & 31;
    const int half = lane >> 4;
    const unsigned fl = lane & 15;
    const int row  = gw * 2 + half;
    if (row >= N_NODES) return;

    int p   = __ldg(&g_rowptr[row]);
    int end = __ldg(&g_rowptr[row + 1]);

    float4 acc = make_float4(0.f, 0.f, 0.f, 0.f);

    #define GATHER(e) __ldg((((e).x < N_USERS) ? xu : xi_adj) + ((unsigned)(e).x * D4 + fl))
    #define FMA4(v, t) do { \
        acc.x = fmaf((v), (t).x, acc.x); \
        acc.y = fmaf((v), (t).y, acc.y); \
        acc.z = fmaf((v), (t).z, acc.z); \
        acc.w = fmaf((v), (t).w, acc.w); } while (0)

    // software-pipelined unroll-4: edge quad for trip i+1 loads before FMAs of trip i
    if (p + 4 <= end) {
        int2 e0 = __ldg(&g_edges[p + 0]);
        int2 e1 = __ldg(&g_edges[p + 1]);
        int2 e2 = __ldg(&g_edges[p + 2]);
        int2 e3 = __ldg(&g_edges[p + 3]);
        for (; p + 8 <= end; p += 4) {
            const float4 t0 = GATHER(e0);
            const float4 t1 = GATHER(e1);
            const float4 t2 = GATHER(e2);
            const float4 t3 = GATHER(e3);
            const int2 n0 = __ldg(&g_edges[p + 4]);
            const int2 n1 = __ldg(&g_edges[p + 5]);
            const int2 n2 = __ldg(&g_edges[p + 6]);
            const int2 n3 = __ldg(&g_edges[p + 7]);
            FMA4(__int_as_float(e0.y), t0);
            FMA4(__int_as_float(e1.y), t1);
            FMA4(__int_as_float(e2.y), t2);
            FMA4(__int_as_float(e3.y), t3);
            e0 = n0; e1 = n1; e2 = n2; e3 = n3;
        }
        const float4 t0 = GATHER(e0);
        const float4 t1 = GATHER(e1);
        const float4 t2 = GATHER(e2);
        const float4 t3 = GATHER(e3);
        FMA4(__int_as_float(e0.y), t0);
        FMA4(__int_as_float(e1.y), t1);
        FMA4(__int_as_float(e2.y), t2);
        FMA4(__int_as_float(e3.y), t3);
        p += 4;
    }
    // remainder: 0-3 edges
    for (; p < end; ++p) {
        const int2 e0 = __ldg(&g_edges[p]);
        const float4 t0 = GATHER(e0);
        FMA4(__int_as_float(e0.y), t0);
    }
    #undef GATHER
    #undef FMA4

    // noise loaded after the loop: registers not live across the edge walk;
    // latency hidden by other resident warps.
    const size_t off = (size_t)row * D4 + fl;
    const float4 nk  = __ldcs(noise + off);

    // noise perturbation: ego += sign(ego) * (n / max(||n||, 1e-12)) * EPS
    float ss = nk.x * nk.x + nk.y * nk.y + nk.z * nk.z + nk.w * nk.w;
    #pragma unroll
    for (int m = 8; m; m >>= 1) ss += __shfl_xor_sync(0xffffffffu, ss, m);
    const float inv = EPS / fmaxf(sqrtf(ss), 1e-12f);
    float4 r = acc;
    r.x += ((acc.x > 0.f) ? 1.f : ((acc.x < 0.f) ? -1.f : 0.f)) * nk.x * inv;
    r.y += ((acc.y > 0.f) ? 1.f : ((acc.y < 0.f) ? -1.f : 0.f)) * nk.y * inv;
    r.z += ((acc.z > 0.f) ? 1.f : ((acc.z < 0.f) ? -1.f : 0.f)) * nk.z * inv;
    r.w += ((acc.w > 0.f) ? 1.f : ((acc.w < 0.f) ? -1.f : 0.f)) * nk.w * inv;

    if (K == 0) {
        yout[off] = r;                                     // ego1 (reused next layer)
        __stcs(out4 + (size_t)N_NODES * D4 + off, r);      // CL region: stream out
    } else if (K == 1) {
        yout[off] = r;                                     // ego2
    } else {
        const float4 pa = __ldcs(prevA + off);             // ego1: last use
        const float4 pb = __ldg(prevB + off);              // ego2: L2-hot
        const float third = 1.f / 3.f;
        float4 f;
        f.x = (pa.x + pb.x + r.x) * third;
        f.y = (pa.y + pb.y + r.y) * third;
        f.z = (pa.z + pb.z + r.z) * third;
        f.w = (pa.w + pb.w + r.w) * third;
        __stcs(out4 + off, f);                             // final region: stream out
    }
}

// ---------------- launch ------------------------------------------------------
extern "C" void kernel_launch(void* const* d_in, const int* in_sizes, int n_in,
                              void* d_out, int out_size) {
    const float* user_emb = (const float*)d_in[0];
    const float* item_emb = (const float*)d_in[1];
    const float* adj_vals = (const float*)d_in[2];
    const float* noise    = (const float*)d_in[3];
    const int*   adj_rows = (const int*)d_in[4];
    const int*   adj_cols = (const int*)d_in[5];
    float4* out4 = (float4*)d_out;

    // --- build CSR from COO ---
    k_hist<<<NNZ / 256, 256>>>(adj_rows);
    k_scan<<<NB_SCAN, SCAN_BS>>>();
    k_scatter<<<NNZ / 256, 256>>>(adj_rows, adj_cols, adj_vals);

    static float4* ego1 = nullptr;
    static float4* ego2 = nullptr;
    if (!ego1) {
        void* p;
        cudaGetSymbolAddress(&p, g_ego1); ego1 = (float4*)p;
        cudaGetSymbolAddress(&p, g_ego2); ego2 = (float4*)p;
    }

    const float4* noise4 = (const float4*)noise;
    const int threads = 256;                               // 8 warps = 16 rows/block
    const int blocks  = N_NODES / 16;                      // 10000

    // layer 0: split tables; xi_adj = item_emb - N_USERS*D4 (pointer only formed)
    k_spmm<0><<<blocks, threads>>>((const float4*)user_emb,
                                   (const float4*)item_emb - (size_t)N_USERS * D4,
                                   noise4,
                                   nullptr, nullptr, ego1, out4);
    // layer 1: x = ego1 contiguous -> xi_adj == xu
    k_spmm<1><<<blocks, threads>>>((const float4*)ego1,
                                   (const float4*)ego1,
                                   noise4 + (size_t)1 * N_NODES * D4,
                                   nullptr, nullptr, ego2, out4);
    // layer 2: x = ego2; epilogue writes final = (ego1+ego2+ego3)/3
    k_spmm<2><<<blocks, threads>>>((const float4*)ego2,
                                   (const float4*)ego2,
                                   noise4 + (size_t)2 * N_NODES * D4,
                                   (const float4*)ego1, (const float4*)ego2,
                                   nullptr, out4);
}